// round 3
// baseline (speedup 1.0000x reference)
#include <cuda_runtime.h>
#include <cuda_bf16.h>

// Problem constants
#define N_NODES   100000
#define N_EDGES   1600000
#define DIM       128
#define N_GRAPHS  1024

// ---------------- scratch (__device__ globals: allocation-free) ----------------
__device__ float g_bufA[(size_t)N_NODES * DIM];   // 51.2 MB
__device__ float g_bufB[(size_t)N_NODES * DIM];   // 51.2 MB
__device__ int   g_cnt[N_NODES];                  // in-degree (edges only)
__device__ float g_dinv[N_NODES];                 // rsqrt(deg+1)
__device__ int   g_rowptr[N_NODES + 1];
__device__ int   g_cursor[N_NODES];
__device__ int   g_srcsorted[N_EDGES];
__device__ float g_pool[N_GRAPHS * DIM];
__device__ int   g_cntg[N_GRAPHS];

// ---------------- init / zero ----------------
__global__ void zero_kernel() {
    int i = blockIdx.x * blockDim.x + threadIdx.x;
    int stride = gridDim.x * blockDim.x;
    for (int j = i; j < N_NODES; j += stride) g_cnt[j] = 0;
    for (int j = i; j < N_GRAPHS * DIM; j += stride) g_pool[j] = 0.0f;
    for (int j = i; j < N_GRAPHS; j += stride) g_cntg[j] = 0;
}

// ---------------- degree histogram over dst ----------------
__global__ void hist_kernel(const int* __restrict__ dst) {
    int i = blockIdx.x * blockDim.x + threadIdx.x;
    int stride = gridDim.x * blockDim.x;
    for (int e = i; e < N_EDGES; e += stride)
        atomicAdd(&g_cnt[dst[e]], 1);
}

// ---------------- dinv = rsqrt(deg + 1)  (self loop) ----------------
__global__ void dinv_kernel() {
    int i = blockIdx.x * blockDim.x + threadIdx.x;
    if (i < N_NODES)
        g_dinv[i] = rsqrtf((float)(g_cnt[i] + 1));
}

// ---------------- exclusive scan (single block, 1024 threads) ----------------
__global__ void scan_kernel() {
    __shared__ int warp_sums[32];
    __shared__ int s_carry;
    int tid = threadIdx.x, lane = tid & 31, wid = tid >> 5;
    if (tid == 0) s_carry = 0;
    __syncthreads();
    for (int base = 0; base < N_NODES; base += 1024) {
        int i = base + tid;
        int v = (i < N_NODES) ? g_cnt[i] : 0;
        int x = v;
        #pragma unroll
        for (int o = 1; o < 32; o <<= 1) {
            int t = __shfl_up_sync(0xffffffffu, x, o);
            if (lane >= o) x += t;
        }
        if (lane == 31) warp_sums[wid] = x;
        __syncthreads();
        if (wid == 0) {
            int s = warp_sums[lane];
            #pragma unroll
            for (int o = 1; o < 32; o <<= 1) {
                int t = __shfl_up_sync(0xffffffffu, s, o);
                if (lane >= o) s += t;
            }
            warp_sums[lane] = s;
        }
        __syncthreads();
        int offset = s_carry + (wid > 0 ? warp_sums[wid - 1] : 0);
        int excl = offset + x - v;
        if (i < N_NODES) { g_rowptr[i] = excl; g_cursor[i] = excl; }
        __syncthreads();
        if (tid == 0) s_carry += warp_sums[31];
        __syncthreads();
    }
    if (threadIdx.x == 0) g_rowptr[N_NODES] = s_carry;
}

// ---------------- counting-sort fill: CSR by dst, storing src ----------------
__global__ void fill_kernel(const int* __restrict__ src, const int* __restrict__ dst) {
    int i = blockIdx.x * blockDim.x + threadIdx.x;
    int stride = gridDim.x * blockDim.x;
    for (int e = i; e < N_EDGES; e += stride) {
        int d = dst[e];
        int pos = atomicAdd(&g_cursor[d], 1);
        g_srcsorted[pos] = src[e];
    }
}

// ---------------- aggregation: out[d] = dinv[d]^2*in[d] + sum dinv[d]dinv[s]*in[s]
// one warp per node, float4 per lane (32 lanes * 4 = 128 feats)
__global__ void agg_kernel(const float* __restrict__ feat, float* __restrict__ out) {
    int gtid = blockIdx.x * blockDim.x + threadIdx.x;
    int node = gtid >> 5;
    int lane = gtid & 31;
    if (node >= N_NODES) return;

    float di = g_dinv[node];
    const float4* self_row = reinterpret_cast<const float4*>(feat + (size_t)node * DIM);
    float4 v = self_row[lane];
    float wsl = di * di;
    float4 acc = make_float4(wsl * v.x, wsl * v.y, wsl * v.z, wsl * v.w);

    int e0 = g_rowptr[node];
    int e1 = g_rowptr[node + 1];
    for (int eb = e0; eb < e1; eb += 32) {
        int nb = min(32, e1 - eb);
        int s = 0; float w = 0.0f;
        if (lane < nb) {
            s = g_srcsorted[eb + lane];
            w = di * g_dinv[s];
        }
        for (int j = 0; j < nb; ++j) {
            int sj  = __shfl_sync(0xffffffffu, s, j);
            float wj = __shfl_sync(0xffffffffu, w, j);
            float4 r = reinterpret_cast<const float4*>(feat + (size_t)sj * DIM)[lane];
            acc.x += wj * r.x; acc.y += wj * r.y;
            acc.z += wj * r.z; acc.w += wj * r.w;
        }
    }
    reinterpret_cast<float4*>(out + (size_t)node * DIM)[lane] = acc;
}

// ---------------- fused GEMM + bias + optional ReLU ----------------
// C[M,128] = act(A[M,128] @ W[128,128] + b)
#define BM 64
#define BK 32
__global__ void gemm_bias_act(const float* __restrict__ A, const float* __restrict__ W,
                              const float* __restrict__ bias, float* __restrict__ C,
                              int M, int relu) {
    __shared__ float As[BK][BM];    // transposed A tile
    __shared__ float Ws[BK][DIM];
    int tid = threadIdx.x;          // 256
    int tx = tid & 31;              // col group (4 cols)
    int ty = tid >> 5;              // row group (8 rows)
    int row0 = blockIdx.x * BM;

    float acc[8][4];
    #pragma unroll
    for (int i = 0; i < 8; ++i)
        #pragma unroll
        for (int j = 0; j < 4; ++j) acc[i][j] = 0.0f;

    for (int k0 = 0; k0 < DIM; k0 += BK) {
        // load A tile (64 x 32), transposed into As[k][r]
        #pragma unroll
        for (int i = 0; i < 2; ++i) {
            int f4 = tid * 2 + i;            // 0..511
            int r = f4 >> 3;                 // 8 float4 per row
            int c = (f4 & 7) * 4;
            int grow = min(row0 + r, M - 1); // clamp (partial last block)
            float4 v = reinterpret_cast<const float4*>(A + (size_t)grow * DIM + k0)[c >> 2];
            As[c + 0][r] = v.x; As[c + 1][r] = v.y;
            As[c + 2][r] = v.z; As[c + 3][r] = v.w;
        }
        // load W tile (32 x 128) -- contiguous
        const float4* Wg = reinterpret_cast<const float4*>(W + (size_t)k0 * DIM);
        float4* Wsv = reinterpret_cast<float4*>(&Ws[0][0]);
        #pragma unroll
        for (int i = 0; i < 4; ++i) {
            int f4 = i * 256 + tid;
            Wsv[f4] = Wg[f4];
        }
        __syncthreads();

        #pragma unroll
        for (int k = 0; k < BK; ++k) {
            float4 w  = *reinterpret_cast<const float4*>(&Ws[k][tx * 4]);
            float4 a0 = *reinterpret_cast<const float4*>(&As[k][ty * 8]);
            float4 a1 = *reinterpret_cast<const float4*>(&As[k][ty * 8 + 4]);
            float ar[8] = {a0.x, a0.y, a0.z, a0.w, a1.x, a1.y, a1.z, a1.w};
            #pragma unroll
            for (int i = 0; i < 8; ++i) {
                acc[i][0] += ar[i] * w.x;
                acc[i][1] += ar[i] * w.y;
                acc[i][2] += ar[i] * w.z;
                acc[i][3] += ar[i] * w.w;
            }
        }
        __syncthreads();
    }

    float4 b = *reinterpret_cast<const float4*>(&bias[tx * 4]);
    #pragma unroll
    for (int i = 0; i < 8; ++i) {
        int row = row0 + ty * 8 + i;
        if (row < M) {
            float4 o;
            o.x = acc[i][0] + b.x; o.y = acc[i][1] + b.y;
            o.z = acc[i][2] + b.z; o.w = acc[i][3] + b.w;
            if (relu) {
                o.x = fmaxf(o.x, 0.0f); o.y = fmaxf(o.y, 0.0f);
                o.z = fmaxf(o.z, 0.0f); o.w = fmaxf(o.w, 0.0f);
            }
            reinterpret_cast<float4*>(C + (size_t)row * DIM)[tx] = o;
        }
    }
}

// ---------------- mean-pool accumulate (atomic) ----------------
__global__ void pool_kernel(const float* __restrict__ feat, const int* __restrict__ batch) {
    int node = blockIdx.x;
    int j = threadIdx.x;   // 128
    int g = batch[node];
    atomicAdd(&g_pool[g * DIM + j], feat[(size_t)node * DIM + j]);
    if (j == 0) atomicAdd(&g_cntg[g], 1);
}

// ---------------- final small GEMM: out = (pool/cnt) @ W2 + b2 ----------------
__global__ void final_gemm(const float* __restrict__ W2, const float* __restrict__ b2,
                           float* __restrict__ out) {
    __shared__ float p[DIM];
    int g = blockIdx.x;
    int j = threadIdx.x;   // 128
    float cnt = fmaxf((float)g_cntg[g], 1.0f);
    p[j] = g_pool[g * DIM + j] / cnt;
    __syncthreads();
    float acc = b2[j];
    #pragma unroll 8
    for (int k = 0; k < DIM; ++k)
        acc += p[k] * W2[k * DIM + j];
    out[g * DIM + j] = acc;
}

// ---------------- launch ----------------
extern "C" void kernel_launch(void* const* d_in, const int* in_sizes, int n_in,
                              void* d_out, int out_size) {
    const float* x    = (const float*)d_in[0];
    const int*   ei   = (const int*)d_in[1];
    const int*   batch = (const int*)d_in[2];
    const float* W1   = (const float*)d_in[3];
    const float* b1   = (const float*)d_in[4];
    const float* W2   = (const float*)d_in[5];
    const float* b2   = (const float*)d_in[6];
    float* out = (float*)d_out;

    const int* src = ei;            // edge_index[0]
    const int* dst = ei + N_EDGES;  // edge_index[1]

    float* bufA; cudaGetSymbolAddress((void**)&bufA, g_bufA);
    float* bufB; cudaGetSymbolAddress((void**)&bufB, g_bufB);

    zero_kernel<<<512, 256>>>();
    hist_kernel<<<2048, 256>>>(dst);
    dinv_kernel<<<(N_NODES + 255) / 256, 256>>>();
    scan_kernel<<<1, 1024>>>();
    fill_kernel<<<2048, 256>>>(src, dst);

    // layer 1: aggregate(x) -> bufA;  bufB = relu(bufA @ W1 + b1)
    int agg_blocks = (N_NODES * 32 + 255) / 256;
    agg_kernel<<<agg_blocks, 256>>>(x, bufA);
    gemm_bias_act<<<(N_NODES + BM - 1) / BM, 256>>>(bufA, W1, b1, bufB, N_NODES, 1);

    // layer 2: aggregate(bufB) -> bufA  (W2 deferred past pooling)
    agg_kernel<<<agg_blocks, 256>>>(bufB, bufA);

    // pool mean, then tiny GEMM with W2 + b2
    pool_kernel<<<N_NODES, DIM>>>(bufA, batch);
    final_gemm<<<N_GRAPHS, DIM>>>(W2, b2, out);
}

// round 4
// speedup vs baseline: 1.3479x; 1.3479x over previous
#include <cuda_runtime.h>
#include <cuda_bf16.h>

// Problem constants
#define N_NODES   100000
#define N_EDGES   1600000
#define DIM       128
#define N_GRAPHS  1024
#define SCAN_BLOCKS 98          // ceil(100000/1024)

// ---------------- scratch (__device__ globals: allocation-free) ----------------
__device__ float g_bufA[(size_t)N_NODES * DIM];   // 51.2 MB
__device__ float g_bufB[(size_t)N_NODES * DIM];   // 51.2 MB
__device__ int   g_cnt[N_NODES];                  // in-degree (edges only)
__device__ float g_dinv[N_NODES];                 // rsqrt(deg+1)
__device__ int   g_rowptr[N_NODES + 1];
__device__ int   g_cursor[N_NODES];
__device__ int   g_srcsorted[N_EDGES];
__device__ int   g_blocksums[SCAN_BLOCKS];
__device__ int   g_blockoff[SCAN_BLOCKS];

// ---------------- zero in-degree ----------------
__global__ void zero_kernel() {
    int i = blockIdx.x * blockDim.x + threadIdx.x;
    if (i < N_NODES) g_cnt[i] = 0;
}

// ---------------- degree histogram over dst ----------------
__global__ void hist_kernel(const int* __restrict__ dst) {
    int i = blockIdx.x * blockDim.x + threadIdx.x;
    int stride = gridDim.x * blockDim.x;
    for (int e = i; e < N_EDGES; e += stride)
        atomicAdd(&g_cnt[dst[e]], 1);
}

// ---------------- scan phase A: per-block exclusive scan + dinv ----------------
__global__ void scanA_kernel() {
    __shared__ int warp_sums[32];
    int tid = threadIdx.x, lane = tid & 31, wid = tid >> 5;
    int i = blockIdx.x * 1024 + tid;
    int v = (i < N_NODES) ? g_cnt[i] : 0;
    if (i < N_NODES) g_dinv[i] = rsqrtf((float)(v + 1));

    int x = v;
    #pragma unroll
    for (int o = 1; o < 32; o <<= 1) {
        int t = __shfl_up_sync(0xffffffffu, x, o);
        if (lane >= o) x += t;
    }
    if (lane == 31) warp_sums[wid] = x;
    __syncthreads();
    if (wid == 0) {
        int s = warp_sums[lane];
        #pragma unroll
        for (int o = 1; o < 32; o <<= 1) {
            int t = __shfl_up_sync(0xffffffffu, s, o);
            if (lane >= o) s += t;
        }
        warp_sums[lane] = s;
    }
    __syncthreads();
    int excl = (wid > 0 ? warp_sums[wid - 1] : 0) + x - v;
    if (i < N_NODES) g_rowptr[i] = excl;
    if (tid == 0) g_blocksums[blockIdx.x] = warp_sums[31];
}

// ---------------- scan phase B: scan the 98 block sums (1 block, 128 thr) ----
__global__ void scanB_kernel() {
    __shared__ int s[128];
    int tid = threadIdx.x;
    s[tid] = (tid < SCAN_BLOCKS) ? g_blocksums[tid] : 0;
    __syncthreads();
    // Hillis-Steele inclusive
    #pragma unroll
    for (int o = 1; o < 128; o <<= 1) {
        int t = (tid >= o) ? s[tid - o] : 0;
        __syncthreads();
        s[tid] += t;
        __syncthreads();
    }
    if (tid < SCAN_BLOCKS)
        g_blockoff[tid] = (tid > 0) ? s[tid - 1] : 0;   // exclusive
}

// ---------------- scan phase C: add block offsets, init cursor -------------
__global__ void scanC_kernel() {
    int i = blockIdx.x * 1024 + threadIdx.x;
    if (i < N_NODES) {
        int r = g_rowptr[i] + g_blockoff[blockIdx.x];
        g_rowptr[i] = r;
        g_cursor[i] = r;
    }
    if (i == 0) g_rowptr[N_NODES] = N_EDGES;  // total in-degree == #edges
}

// ---------------- counting-sort fill: CSR by dst, storing src ----------------
__global__ void fill_kernel(const int* __restrict__ src, const int* __restrict__ dst) {
    int i = blockIdx.x * blockDim.x + threadIdx.x;
    int stride = gridDim.x * blockDim.x;
    for (int e = i; e < N_EDGES; e += stride) {
        int d = dst[e];
        int pos = atomicAdd(&g_cursor[d], 1);
        g_srcsorted[pos] = src[e];
    }
}

// ---------------- aggregation: out[d] = dinv[d]^2*in[d] + sum dinv[d]dinv[s]*in[s]
// one warp per node, float4 per lane (32 lanes * 4 = 128 feats)
__global__ void agg_kernel(const float* __restrict__ feat, float* __restrict__ out) {
    int gtid = blockIdx.x * blockDim.x + threadIdx.x;
    int node = gtid >> 5;
    int lane = gtid & 31;
    if (node >= N_NODES) return;

    float di = g_dinv[node];
    const float4* self_row = reinterpret_cast<const float4*>(feat + (size_t)node * DIM);
    float4 v = self_row[lane];
    float wsl = di * di;
    float4 acc = make_float4(wsl * v.x, wsl * v.y, wsl * v.z, wsl * v.w);

    int e0 = g_rowptr[node];
    int e1 = g_rowptr[node + 1];
    for (int eb = e0; eb < e1; eb += 32) {
        int nb = min(32, e1 - eb);
        int s = 0; float w = 0.0f;
        if (lane < nb) {
            s = g_srcsorted[eb + lane];
            w = di * g_dinv[s];
        }
        for (int j = 0; j < nb; ++j) {
            int sj  = __shfl_sync(0xffffffffu, s, j);
            float wj = __shfl_sync(0xffffffffu, w, j);
            float4 r = reinterpret_cast<const float4*>(feat + (size_t)sj * DIM)[lane];
            acc.x += wj * r.x; acc.y += wj * r.y;
            acc.z += wj * r.z; acc.w += wj * r.w;
        }
    }
    reinterpret_cast<float4*>(out + (size_t)node * DIM)[lane] = acc;
}

// ---------------- fused GEMM + bias + optional ReLU ----------------
// C[M,128] = act(A[M,128] @ W[128,128] + b)
#define BM 64
#define BK 32
__global__ void gemm_bias_act(const float* __restrict__ A, const float* __restrict__ W,
                              const float* __restrict__ bias, float* __restrict__ C,
                              int M, int relu) {
    __shared__ float As[BK][BM];    // transposed A tile
    __shared__ float Ws[BK][DIM];
    int tid = threadIdx.x;          // 256
    int tx = tid & 31;              // col group (4 cols)
    int ty = tid >> 5;              // row group (8 rows)
    int row0 = blockIdx.x * BM;

    float acc[8][4];
    #pragma unroll
    for (int i = 0; i < 8; ++i)
        #pragma unroll
        for (int j = 0; j < 4; ++j) acc[i][j] = 0.0f;

    for (int k0 = 0; k0 < DIM; k0 += BK) {
        #pragma unroll
        for (int i = 0; i < 2; ++i) {
            int f4 = tid * 2 + i;            // 0..511
            int r = f4 >> 3;                 // 8 float4 per row
            int c = (f4 & 7) * 4;
            int grow = min(row0 + r, M - 1); // clamp (partial last block)
            float4 v = reinterpret_cast<const float4*>(A + (size_t)grow * DIM + k0)[c >> 2];
            As[c + 0][r] = v.x; As[c + 1][r] = v.y;
            As[c + 2][r] = v.z; As[c + 3][r] = v.w;
        }
        const float4* Wg = reinterpret_cast<const float4*>(W + (size_t)k0 * DIM);
        float4* Wsv = reinterpret_cast<float4*>(&Ws[0][0]);
        #pragma unroll
        for (int i = 0; i < 4; ++i) {
            int f4 = i * 256 + tid;
            Wsv[f4] = Wg[f4];
        }
        __syncthreads();

        #pragma unroll
        for (int k = 0; k < BK; ++k) {
            float4 w  = *reinterpret_cast<const float4*>(&Ws[k][tx * 4]);
            float4 a0 = *reinterpret_cast<const float4*>(&As[k][ty * 8]);
            float4 a1 = *reinterpret_cast<const float4*>(&As[k][ty * 8 + 4]);
            float ar[8] = {a0.x, a0.y, a0.z, a0.w, a1.x, a1.y, a1.z, a1.w};
            #pragma unroll
            for (int i = 0; i < 8; ++i) {
                acc[i][0] += ar[i] * w.x;
                acc[i][1] += ar[i] * w.y;
                acc[i][2] += ar[i] * w.z;
                acc[i][3] += ar[i] * w.w;
            }
        }
        __syncthreads();
    }

    float4 b = *reinterpret_cast<const float4*>(&bias[tx * 4]);
    #pragma unroll
    for (int i = 0; i < 8; ++i) {
        int row = row0 + ty * 8 + i;
        if (row < M) {
            float4 o;
            o.x = acc[i][0] + b.x; o.y = acc[i][1] + b.y;
            o.z = acc[i][2] + b.z; o.w = acc[i][3] + b.w;
            if (relu) {
                o.x = fmaxf(o.x, 0.0f); o.y = fmaxf(o.y, 0.0f);
                o.z = fmaxf(o.z, 0.0f); o.w = fmaxf(o.w, 0.0f);
            }
            reinterpret_cast<float4*>(C + (size_t)row * DIM)[tx] = o;
        }
    }
}

// ---------------- fused mean-pool (sorted batch, binary search) + W2 GEMM ----
// One block per graph: out[g] = mean_{batch[n]==g}(feat[n]) @ W2 + b2
__global__ void pool_gemm_kernel(const float* __restrict__ feat,
                                 const int* __restrict__ batch,
                                 const float* __restrict__ W2,
                                 const float* __restrict__ b2,
                                 float* __restrict__ out) {
    __shared__ float p[DIM];
    int g = blockIdx.x;
    int j = threadIdx.x;   // 128

    // binary search: first index with batch[i] >= g, and >= g+1 (batch sorted)
    int lo = 0, hi = N_NODES;
    while (lo < hi) { int m = (lo + hi) >> 1; if (batch[m] < g) lo = m + 1; else hi = m; }
    int start = lo;
    hi = N_NODES;
    while (lo < hi) { int m = (lo + hi) >> 1; if (batch[m] < g + 1) lo = m + 1; else hi = m; }
    int end = lo;

    float acc = 0.0f;
    for (int n = start; n < end; ++n)
        acc += feat[(size_t)n * DIM + j];
    float cnt = fmaxf((float)(end - start), 1.0f);
    p[j] = acc / cnt;
    __syncthreads();

    float o = b2[j];
    #pragma unroll 8
    for (int k = 0; k < DIM; ++k)
        o += p[k] * W2[k * DIM + j];
    out[g * DIM + j] = o;
}

// ---------------- launch ----------------
extern "C" void kernel_launch(void* const* d_in, const int* in_sizes, int n_in,
                              void* d_out, int out_size) {
    const float* x     = (const float*)d_in[0];
    const int*   ei    = (const int*)d_in[1];
    const int*   batch = (const int*)d_in[2];
    const float* W1    = (const float*)d_in[3];
    const float* b1    = (const float*)d_in[4];
    const float* W2    = (const float*)d_in[5];
    const float* b2    = (const float*)d_in[6];
    float* out = (float*)d_out;

    const int* src = ei;            // edge_index[0]
    const int* dst = ei + N_EDGES;  // edge_index[1]

    float* bufA; cudaGetSymbolAddress((void**)&bufA, g_bufA);
    float* bufB; cudaGetSymbolAddress((void**)&bufB, g_bufB);

    zero_kernel<<<(N_NODES + 1023) / 1024, 1024>>>();
    hist_kernel<<<2048, 256>>>(dst);
    scanA_kernel<<<SCAN_BLOCKS, 1024>>>();
    scanB_kernel<<<1, 128>>>();
    scanC_kernel<<<SCAN_BLOCKS, 1024>>>();
    fill_kernel<<<2048, 256>>>(src, dst);

    // layer 1: aggregate(x) -> bufA;  bufB = relu(bufA @ W1 + b1)
    int agg_blocks = (N_NODES * 32 + 255) / 256;
    agg_kernel<<<agg_blocks, 256>>>(x, bufA);
    gemm_bias_act<<<(N_NODES + BM - 1) / BM, 256>>>(bufA, W1, b1, bufB, N_NODES, 1);

    // layer 2: aggregate(bufB) -> bufA  (W2 deferred past pooling)
    agg_kernel<<<agg_blocks, 256>>>(bufB, bufA);

    // fused mean-pool + W2 GEMM + b2
    pool_gemm_kernel<<<N_GRAPHS, DIM>>>(bufA, batch, W2, b2, out);
}